// round 1
// baseline (speedup 1.0000x reference)
#include <cuda_runtime.h>
#include <cstddef>

// Problem constants (bigram trie, fixed shapes from reference)
#define V_  32768
#define C_  32
#define B_  32
#define K_  (V_ * C_)        // 1048576 bigram nodes
#define X_  (K_ + 1)         // pointers length
#define G_  V_               // unigram count
#define U_  (V_ + 1)         // first bigram node index

// Fill: out[b, v] = logs[X+G+h_b] + logs[v]
// Grid: B_*V_ / (256*4) = 1024 blocks, 256 threads, float4 per thread.
// Each block covers 1024 consecutive v within a single row b.
__global__ void __launch_bounds__(256) llm_fill_kernel(
    const int* __restrict__ hist,
    const int* __restrict__ idx,
    const float* __restrict__ logs,
    float* __restrict__ out)
{
    const int blk = blockIdx.x;            // 0..1023
    const int b = blk >> 5;                // 32 chunks per row (32768/1024)
    const int chunk = blk & 31;
    const int h = hist[(idx[0] - 1) * B_ + b];
    const float backoff = logs[(size_t)X_ + G_ + h];

    const int v0 = chunk * 1024 + threadIdx.x * 4;
    float4 lv = *reinterpret_cast<const float4*>(logs + v0);
    float4 o;
    o.x = backoff + lv.x;
    o.y = backoff + lv.y;
    o.z = backoff + lv.z;
    o.w = backoff + lv.w;
    *reinterpret_cast<float4*>(out + (size_t)b * V_ + v0) = o;
}

// Scatter: for each (b, j) child, out[b, child_tok] = logs[child_node]
__global__ void __launch_bounds__(256) llm_scatter_kernel(
    const int* __restrict__ hist,
    const int* __restrict__ idx,
    const int* __restrict__ pointers,
    const int* __restrict__ ids,
    const float* __restrict__ logs,
    float* __restrict__ out)
{
    const int t = blockIdx.x * blockDim.x + threadIdx.x;   // 0..B_*C_-1
    if (t >= B_ * C_) return;
    const int b = t / C_;
    const int j = t % C_;
    const int h = hist[(idx[0] - 1) * B_ + b];
    const int off = pointers[h];
    const int nc = pointers[h + 1] - off + 1;
    if (j < nc) {
        const int node = h + off + j;          // bigram node id
        const int tok = ids[node - U_];        // child token
        out[(size_t)b * V_ + tok] = logs[node];
    }
}

extern "C" void kernel_launch(void* const* d_in, const int* in_sizes, int n_in,
                              void* d_out, int out_size)
{
    const int*   hist     = (const int*)d_in[0];   // (S, B) int32
    const int*   idx      = (const int*)d_in[1];   // scalar int32
    const int*   pointers = (const int*)d_in[2];   // (X,) int32
    const int*   ids      = (const int*)d_in[3];   // (K,) int32
    const float* logs     = (const float*)d_in[4]; // (L,) float32
    float*       out      = (float*)d_out;         // (B, V) float32

    (void)in_sizes; (void)n_in; (void)out_size;

    // Fill: 1024 blocks x 256 threads x 4 floats = B*V elements
    llm_fill_kernel<<<(B_ * V_) / (256 * 4), 256>>>(hist, idx, logs, out);
    // Scatter: 1024 overrides (stream-ordered after fill)
    llm_scatter_kernel<<<(B_ * C_ + 255) / 256, 256>>>(hist, idx, pointers, ids, logs, out);
}

// round 2
// speedup vs baseline: 1.0037x; 1.0037x over previous
#include <cuda_runtime.h>
#include <cstddef>

// Problem constants (bigram trie, fixed shapes from reference)
#define V_  32768
#define C_  32
#define B_  32
#define K_  (V_ * C_)        // 1048576 bigram nodes
#define X_  (K_ + 1)         // pointers length
#define G_  V_               // unigram count
#define U_  (V_ + 1)         // first bigram node index

// Fused fill + override.
// Grid: 1024 blocks (32 rows x 32 chunks), 256 threads, 4 floats/thread.
// out[b, v] = logs[X+G+h_b] + logs[v], overridden with logs[child_node]
// where child token == v for each of the <=32 children of h_b.
__global__ void __launch_bounds__(256) llm_fused_kernel(
    const int* __restrict__ hist,
    const int* __restrict__ idx,
    const int* __restrict__ pointers,
    const int* __restrict__ ids,
    const float* __restrict__ logs,
    float* __restrict__ out)
{
    __shared__ int   s_tok[C_];
    __shared__ float s_lp[C_];
    __shared__ float s_backoff;

    const int blk   = blockIdx.x;          // 0..1023
    const int b     = blk >> 5;            // row (32 chunks per row)
    const int chunk = blk & 31;

    // Warp 0 stages per-row child data into smem.
    if (threadIdx.x < C_) {
        const int h   = hist[(idx[0] - 1) * B_ + b];
        const int off = pointers[h];
        const int nc  = pointers[h + 1] - off + 1;
        const int node = h + off + threadIdx.x;
        const bool valid = threadIdx.x < nc;
        s_tok[threadIdx.x] = valid ? ids[node - U_] : -1;
        s_lp[threadIdx.x]  = valid ? logs[node] : 0.0f;
        if (threadIdx.x == 0)
            s_backoff = logs[(size_t)X_ + G_ + h];
    }
    __syncthreads();

    const float backoff = s_backoff;
    const int v0 = chunk * 1024 + threadIdx.x * 4;

    float4 lv = *reinterpret_cast<const float4*>(logs + v0);
    float r0 = backoff + lv.x;
    float r1 = backoff + lv.y;
    float r2 = backoff + lv.z;
    float r3 = backoff + lv.w;

    // Patch any child token falling in [v0, v0+4).
    #pragma unroll
    for (int j = 0; j < C_; j++) {
        const unsigned d = (unsigned)(s_tok[j] - v0);
        if (d < 4u) {
            const float lp = s_lp[j];
            if (d == 0u) r0 = lp;
            else if (d == 1u) r1 = lp;
            else if (d == 2u) r2 = lp;
            else r3 = lp;
        }
    }

    float4 o; o.x = r0; o.y = r1; o.z = r2; o.w = r3;
    *reinterpret_cast<float4*>(out + (size_t)b * V_ + v0) = o;
}

extern "C" void kernel_launch(void* const* d_in, const int* in_sizes, int n_in,
                              void* d_out, int out_size)
{
    const int*   hist     = (const int*)d_in[0];   // (S, B) int32
    const int*   idx      = (const int*)d_in[1];   // scalar int32
    const int*   pointers = (const int*)d_in[2];   // (X,) int32
    const int*   ids      = (const int*)d_in[3];   // (K,) int32
    const float* logs     = (const float*)d_in[4]; // (L,) float32
    float*       out      = (float*)d_out;         // (B, V) float32

    (void)in_sizes; (void)n_in; (void)out_size;

    llm_fused_kernel<<<(B_ * V_) / (256 * 4), 256>>>(hist, idx, pointers, ids, logs, out);
}

// round 3
// speedup vs baseline: 1.2651x; 1.2605x over previous
#include <cuda_runtime.h>
#include <cstddef>

// Problem constants (bigram trie, fixed shapes from reference)
#define V_  32768
#define C_  32
#define B_  32
#define K_  (V_ * C_)        // 1048576 bigram nodes
#define X_  (K_ + 1)         // pointers length
#define G_  V_               // unigram count
#define U_  (V_ + 1)         // first bigram node index

// Fused fill + sparse override.
// Grid: 1024 blocks (32 rows x 32 chunks of 1024 v's), 256 threads, float4/thread.
// Phase 1: out[b, v] = logs[X+G+h_b] + logs[v]   (streaming, coalesced)
// Phase 2: threads 0..31 override the (avg 1 per block) child tokens that
//          fall inside this block's v-window with logs[child_node].
__global__ void __launch_bounds__(256) llm_fused_kernel(
    const int* __restrict__ hist,
    const int* __restrict__ idx,
    const int* __restrict__ pointers,
    const int* __restrict__ ids,
    const float* __restrict__ logs,
    float* __restrict__ out)
{
    const int blk   = blockIdx.x;          // 0..1023
    const int b     = blk >> 5;            // row (32 chunks per row)
    const int chunk = blk & 31;

    // Uniform loads (L1/L2 hits after first wave)
    const int h = hist[(idx[0] - 1) * B_ + b];
    const float backoff = __ldg(logs + (size_t)X_ + G_ + h);

    const int v0 = chunk * 1024 + threadIdx.x * 4;
    float4 lv = *reinterpret_cast<const float4*>(logs + v0);
    float4 o;
    o.x = backoff + lv.x;
    o.y = backoff + lv.y;
    o.z = backoff + lv.z;
    o.w = backoff + lv.w;
    *reinterpret_cast<float4*>(out + (size_t)b * V_ + v0) = o;

    // Order fill stores before overrides within the block.
    __syncthreads();

    if (threadIdx.x < C_) {
        const int off = pointers[h];
        const int nc  = pointers[h + 1] - off + 1;
        if ((int)threadIdx.x < nc) {
            const int node = h + off + threadIdx.x;   // bigram node id
            const int tok  = ids[node - U_];          // child token id
            if ((tok >> 10) == chunk)                 // falls in this block's window
                out[(size_t)b * V_ + tok] = logs[node];
        }
    }
}

extern "C" void kernel_launch(void* const* d_in, const int* in_sizes, int n_in,
                              void* d_out, int out_size)
{
    const int*   hist     = (const int*)d_in[0];   // (S, B) int32
    const int*   idx      = (const int*)d_in[1];   // scalar int32
    const int*   pointers = (const int*)d_in[2];   // (X,) int32
    const int*   ids      = (const int*)d_in[3];   // (K,) int32
    const float* logs     = (const float*)d_in[4]; // (L,) float32
    float*       out      = (float*)d_out;         // (B, V) float32

    (void)in_sizes; (void)n_in; (void)out_size;

    llm_fused_kernel<<<(B_ * V_) / (256 * 4), 256>>>(hist, idx, pointers, ids, logs, out);
}